// round 4
// baseline (speedup 1.0000x reference)
#include <cuda_runtime.h>
#include <cuda_bf16.h>

#define C_CLASSES 5
#define NREP 4            // shared-table replicas

__device__ double   g_acc[2];   // [0]=num, [1]=den. Zero-init at load; last block resets.
__device__ unsigned g_count;    // blocks-done counter. Zero-init; last block resets.

// Extended table ext[j], j = floor(x)+1 in [0, 6]:
//   ext[0] = -1/(C-1), ext[1..C] = pcnl[0..C-1], ext[C+1] = C/(C-1)
// e2[j] = (ext[j], ext[j+1]) so interp needs one LDS.64.
// pw[t] = (pcnl[t], weight[t]) so target lookup needs one LDS.64.
__device__ __forceinline__ void owe_elem(float x, int t,
                                         const float2* __restrict__ e2,
                                         const float2* __restrict__ pw,
                                         float& num, float& den) {
    float f = floorf(x);
    int   j = (int)f + 1;
    j = max(0, min(j, C_CLASSES));   // j in [0, C]; inputs keep this in-range anyway
    float2 e = e2[j];
    float ip = fmaf(e.y - e.x, x - f, e.x);
    float2 p = pw[t];
    float d  = ip - p.x;
    num = fmaf(d * d, p.y, num);
    den += p.y;
}

__global__ void __launch_bounds__(256)
owe_kernel(const float4* __restrict__ inp4,
           const int4*  __restrict__ tgt4,
           const float* __restrict__ weight,
           const float* __restrict__ dist,
           int n4,
           const float* __restrict__ inp_tail,
           const int*   __restrict__ tgt_tail,
           int tail_start, int n_total,
           float* __restrict__ out) {
    // float2 tables, NREP replicas at stride 8 entries (64B).
    __shared__ float2 s_e2[NREP * 8];   // entries 0..5 used
    __shared__ float2 s_pw[NREP * 8];   // entries 0..4 used

    if (threadIdx.x == 0) {
        float ds[C_CLASSES], cs[C_CLASSES];
        float ext[C_CLASSES + 2], ww[C_CLASSES];
        float c = 0.f;
        #pragma unroll
        for (int i = 0; i < C_CLASSES; i++) { ds[i] = dist[i]; c += ds[i]; cs[i] = c; }
        float inv = 1.0f / (2.0f * cs[C_CLASSES - 1] - ds[0] - ds[C_CLASSES - 1]);
        ext[0] = -1.0f / (float)(C_CLASSES - 1);
        #pragma unroll
        for (int i = 0; i < C_CLASSES; i++) {
            ext[i + 1] = (2.0f * cs[i] - ds[i] - ds[0]) * inv;
            ww[i] = weight[i];
        }
        ext[C_CLASSES + 1] = (float)C_CLASSES / (float)(C_CLASSES - 1);
        #pragma unroll
        for (int r = 0; r < NREP; r++) {
            #pragma unroll
            for (int jj = 0; jj <= C_CLASSES; jj++)
                s_e2[r * 8 + jj] = make_float2(ext[jj], ext[jj + 1]);
            #pragma unroll
            for (int i = 0; i < C_CLASSES; i++)
                s_pw[r * 8 + i] = make_float2(ext[i + 1], ww[i]);
        }
    }
    __syncthreads();

    const int rep = (threadIdx.x & (NREP - 1)) * 8;
    const float2* __restrict__ e2 = s_e2 + rep;
    const float2* __restrict__ pw = s_pw + rep;

    float num = 0.0f, den = 0.0f;

    int tid    = blockIdx.x * blockDim.x + threadIdx.x;
    int stride = gridDim.x * blockDim.x;

    // Unroll x4: 8 LDG.128 front-batched per iteration (MLP=8).
    int i = tid;
    for (; i + 3 * stride < n4; i += 4 * stride) {
        float4 x0 = inp4[i];
        float4 x1 = inp4[i + stride];
        float4 x2 = inp4[i + 2 * stride];
        float4 x3 = inp4[i + 3 * stride];
        int4   t0 = tgt4[i];
        int4   t1 = tgt4[i + stride];
        int4   t2 = tgt4[i + 2 * stride];
        int4   t3 = tgt4[i + 3 * stride];

        owe_elem(x0.x, t0.x, e2, pw, num, den);
        owe_elem(x0.y, t0.y, e2, pw, num, den);
        owe_elem(x0.z, t0.z, e2, pw, num, den);
        owe_elem(x0.w, t0.w, e2, pw, num, den);
        owe_elem(x1.x, t1.x, e2, pw, num, den);
        owe_elem(x1.y, t1.y, e2, pw, num, den);
        owe_elem(x1.z, t1.z, e2, pw, num, den);
        owe_elem(x1.w, t1.w, e2, pw, num, den);
        owe_elem(x2.x, t2.x, e2, pw, num, den);
        owe_elem(x2.y, t2.y, e2, pw, num, den);
        owe_elem(x2.z, t2.z, e2, pw, num, den);
        owe_elem(x2.w, t2.w, e2, pw, num, den);
        owe_elem(x3.x, t3.x, e2, pw, num, den);
        owe_elem(x3.y, t3.y, e2, pw, num, den);
        owe_elem(x3.z, t3.z, e2, pw, num, den);
        owe_elem(x3.w, t3.w, e2, pw, num, den);
    }
    for (; i < n4; i += stride) {
        float4 x0 = inp4[i];
        int4   t0 = tgt4[i];
        owe_elem(x0.x, t0.x, e2, pw, num, den);
        owe_elem(x0.y, t0.y, e2, pw, num, den);
        owe_elem(x0.z, t0.z, e2, pw, num, den);
        owe_elem(x0.w, t0.w, e2, pw, num, den);
    }
    for (int jj = tail_start + tid; jj < n_total; jj += stride) {
        owe_elem(inp_tail[jj], tgt_tail[jj], e2, pw, num, den);
    }

    // Warp reduction
    #pragma unroll
    for (int off = 16; off > 0; off >>= 1) {
        num += __shfl_down_sync(0xFFFFFFFFu, num, off);
        den += __shfl_down_sync(0xFFFFFFFFu, den, off);
    }

    // Block reduction
    __shared__ float s_num[8];
    __shared__ float s_den[8];
    int lane = threadIdx.x & 31;
    int warp = threadIdx.x >> 5;
    if (lane == 0) { s_num[warp] = num; s_den[warp] = den; }
    __syncthreads();
    if (warp == 0) {
        float bn = (lane < (blockDim.x >> 5)) ? s_num[lane] : 0.0f;
        float bd = (lane < (blockDim.x >> 5)) ? s_den[lane] : 0.0f;
        #pragma unroll
        for (int off = 4; off > 0; off >>= 1) {
            bn += __shfl_down_sync(0xFFFFFFFFu, bn, off);
            bd += __shfl_down_sync(0xFFFFFFFFu, bd, off);
        }
        if (lane == 0) {
            atomicAdd(&g_acc[0], (double)bn);
            atomicAdd(&g_acc[1], (double)bd);
            __threadfence();
            unsigned done = atomicAdd(&g_count, 1u);
            if (done == gridDim.x - 1) {
                double fn = __longlong_as_double(
                    atomicExch((unsigned long long*)&g_acc[0], 0ULL));
                double fd = __longlong_as_double(
                    atomicExch((unsigned long long*)&g_acc[1], 0ULL));
                out[0] = (float)(fn / fd);
                atomicExch(&g_count, 0u);
            }
        }
    }
}

extern "C" void kernel_launch(void* const* d_in, const int* in_sizes, int n_in,
                              void* d_out, int out_size) {
    const float* inp  = (const float*)d_in[0];
    const int*   tgt  = (const int*)d_in[1];
    const float* wgt  = (const float*)d_in[2];
    const float* dist = (const float*)d_in[3];
    float* out = (float*)d_out;

    int n  = in_sizes[0];
    int n4 = n >> 2;
    int tail_start = n4 << 2;

    const int threads = 256;
    int blocks = 148 * 8;  // 1184 blocks
    int max_useful = (n4 + threads - 1) / threads;
    if (blocks > max_useful && max_useful > 0) blocks = max_useful;
    if (blocks < 1) blocks = 1;

    owe_kernel<<<blocks, threads>>>((const float4*)inp, (const int4*)tgt,
                                    wgt, dist, n4, inp, tgt, tail_start, n, out);
}

// round 5
// speedup vs baseline: 1.1311x; 1.1311x over previous
#include <cuda_runtime.h>
#include <cuda_bf16.h>

#define C_CLASSES 5

__device__ double   g_acc[2];   // [0]=num, [1]=den. Zero-init at load; last block resets.
__device__ unsigned g_count;    // blocks-done counter. Zero-init; last block resets.

// Extended table ext[j], j = floor(x)+1 in [0, 6]:
//   ext[0] = -1/(C-1), ext[1..C] = pcnl[0..C-1], ext[C+1] = C/(C-1)
// Per-lane register tables: lane L holds ea=ext[L], eb=ext[L+1], p=pcnl[L], w=weight[L].
// Lookups become warp shuffles (conflict-free, per-SMSP issue).
__device__ __forceinline__ void owe_elem(float x, int t,
                                         float r_ea, float r_eb,
                                         float r_p, float r_w,
                                         float& num, float& den) {
    float f = floorf(x);
    int   j = (int)f + 1;
    j = max(0, min(j, C_CLASSES));   // j in [0, C]
    float ea = __shfl_sync(0xFFFFFFFFu, r_ea, j);
    float eb = __shfl_sync(0xFFFFFFFFu, r_eb, j);
    float ip = fmaf(eb - ea, x - f, ea);
    float p  = __shfl_sync(0xFFFFFFFFu, r_p, t);
    float w  = __shfl_sync(0xFFFFFFFFu, r_w, t);
    float d  = ip - p;
    num = fmaf(d * d, w, num);
    den += w;
}

__global__ void __launch_bounds__(256)
owe_kernel(const float4* __restrict__ inp4,
           const int4*  __restrict__ tgt4,
           const float* __restrict__ weight,
           const float* __restrict__ dist,
           int n4,
           const float* __restrict__ inp_tail,
           const int*   __restrict__ tgt_tail,
           int tail_start, int n_total,
           float* __restrict__ out) {
    // Staging tables in smem (read once per thread at startup, then registers).
    __shared__ float s_ext[9];   // ext[0..6], padded
    __shared__ float s_p[8];     // pcnl[0..4], padded
    __shared__ float s_w[8];     // weight[0..4], padded

    if (threadIdx.x == 0) {
        float ds[C_CLASSES], cs[C_CLASSES];
        float c = 0.f;
        #pragma unroll
        for (int i = 0; i < C_CLASSES; i++) { ds[i] = dist[i]; c += ds[i]; cs[i] = c; }
        float inv = 1.0f / (2.0f * cs[C_CLASSES - 1] - ds[0] - ds[C_CLASSES - 1]);
        s_ext[0] = -1.0f / (float)(C_CLASSES - 1);
        #pragma unroll
        for (int i = 0; i < C_CLASSES; i++) {
            float pc = (2.0f * cs[i] - ds[i] - ds[0]) * inv;
            s_ext[i + 1] = pc;
            s_p[i] = pc;
            s_w[i] = weight[i];
        }
        s_ext[C_CLASSES + 1] = (float)C_CLASSES / (float)(C_CLASSES - 1);
        s_ext[C_CLASSES + 2] = 0.0f;   // pad
        s_p[5] = s_p[6] = s_p[7] = 0.0f;
        s_w[5] = s_w[6] = s_w[7] = 0.0f;
    }
    __syncthreads();

    // Per-lane register tables. lane&7 wraps lanes 8..31 harmlessly (never selected).
    int lane = threadIdx.x & 31;
    int l8   = lane & 7;
    float r_ea = s_ext[l8];        // ext[lane] for lane 0..6
    float r_eb = s_ext[l8 + 1];    // ext[lane+1]
    float r_p  = s_p[l8];          // pcnl[lane] for lane 0..4
    float r_w  = s_w[l8];          // weight[lane]

    float num = 0.0f, den = 0.0f;

    int tid    = blockIdx.x * blockDim.x + threadIdx.x;
    int stride = gridDim.x * blockDim.x;

    // Unroll x2: 4 streaming LDG.128 in flight per thread.
    int i = tid;
    for (; i + stride < n4; i += 2 * stride) {
        float4 x0 = __ldcs(&inp4[i]);
        int4   t0 = __ldcs(&tgt4[i]);
        float4 x1 = __ldcs(&inp4[i + stride]);
        int4   t1 = __ldcs(&tgt4[i + stride]);
        owe_elem(x0.x, t0.x, r_ea, r_eb, r_p, r_w, num, den);
        owe_elem(x0.y, t0.y, r_ea, r_eb, r_p, r_w, num, den);
        owe_elem(x0.z, t0.z, r_ea, r_eb, r_p, r_w, num, den);
        owe_elem(x0.w, t0.w, r_ea, r_eb, r_p, r_w, num, den);
        owe_elem(x1.x, t1.x, r_ea, r_eb, r_p, r_w, num, den);
        owe_elem(x1.y, t1.y, r_ea, r_eb, r_p, r_w, num, den);
        owe_elem(x1.z, t1.z, r_ea, r_eb, r_p, r_w, num, den);
        owe_elem(x1.w, t1.w, r_ea, r_eb, r_p, r_w, num, den);
    }
    for (; i < n4; i += stride) {
        float4 x0 = __ldcs(&inp4[i]);
        int4   t0 = __ldcs(&tgt4[i]);
        owe_elem(x0.x, t0.x, r_ea, r_eb, r_p, r_w, num, den);
        owe_elem(x0.y, t0.y, r_ea, r_eb, r_p, r_w, num, den);
        owe_elem(x0.z, t0.z, r_ea, r_eb, r_p, r_w, num, den);
        owe_elem(x0.w, t0.w, r_ea, r_eb, r_p, r_w, num, den);
    }
    for (int jj = tail_start + tid; jj < n_total; jj += stride) {
        owe_elem(inp_tail[jj], tgt_tail[jj], r_ea, r_eb, r_p, r_w, num, den);
    }

    // Warp reduction
    #pragma unroll
    for (int off = 16; off > 0; off >>= 1) {
        num += __shfl_down_sync(0xFFFFFFFFu, num, off);
        den += __shfl_down_sync(0xFFFFFFFFu, den, off);
    }

    // Block reduction
    __shared__ float s_num[8];
    __shared__ float s_den[8];
    int warp = threadIdx.x >> 5;
    if (lane == 0) { s_num[warp] = num; s_den[warp] = den; }
    __syncthreads();
    if (warp == 0) {
        float bn = (lane < (blockDim.x >> 5)) ? s_num[lane] : 0.0f;
        float bd = (lane < (blockDim.x >> 5)) ? s_den[lane] : 0.0f;
        #pragma unroll
        for (int off = 4; off > 0; off >>= 1) {
            bn += __shfl_down_sync(0xFFFFFFFFu, bn, off);
            bd += __shfl_down_sync(0xFFFFFFFFu, bd, off);
        }
        if (lane == 0) {
            atomicAdd(&g_acc[0], (double)bn);
            atomicAdd(&g_acc[1], (double)bd);
            __threadfence();
            unsigned done = atomicAdd(&g_count, 1u);
            if (done == gridDim.x - 1) {
                double fn = __longlong_as_double(
                    atomicExch((unsigned long long*)&g_acc[0], 0ULL));
                double fd = __longlong_as_double(
                    atomicExch((unsigned long long*)&g_acc[1], 0ULL));
                out[0] = (float)(fn / fd);
                atomicExch(&g_count, 0u);
            }
        }
    }
}

extern "C" void kernel_launch(void* const* d_in, const int* in_sizes, int n_in,
                              void* d_out, int out_size) {
    const float* inp  = (const float*)d_in[0];
    const int*   tgt  = (const int*)d_in[1];
    const float* wgt  = (const float*)d_in[2];
    const float* dist = (const float*)d_in[3];
    float* out = (float*)d_out;

    int n  = in_sizes[0];
    int n4 = n >> 2;
    int tail_start = n4 << 2;

    const int threads = 256;
    int blocks = 148 * 8;  // 1184 blocks
    int max_useful = (n4 + threads - 1) / threads;
    if (blocks > max_useful && max_useful > 0) blocks = max_useful;
    if (blocks < 1) blocks = 1;

    owe_kernel<<<blocks, threads>>>((const float4*)inp, (const int4*)tgt,
                                    wgt, dist, n4, inp, tgt, tail_start, n, out);
}

// round 6
// speedup vs baseline: 1.2267x; 1.0844x over previous
#include <cuda_runtime.h>
#include <cuda_bf16.h>

#define C_CLASSES 5
#define NREP 4            // shared-table replicas (stride 8 words -> distinct bank octets)

__device__ double   g_acc[2];   // [0]=num, [1]=den. Zero-init at load; last block resets.
__device__ unsigned g_count;    // blocks-done counter. Zero-init; last block resets.

// Tables indexed by j = floor(x)+1 in [0,6]:
//   ea[j] = ext[j], sl[j] = ext[j+1]-ext[j], where
//   ext[0] = -1/(C-1), ext[1..C] = pcnl[0..C-1], ext[C+1] = C/(C-1)
// Target tables: tp[t]=pcnl[t], tw[t]=weight[t].
__device__ __forceinline__ void owe_elem(float x, int t,
                                         const float* __restrict__ ea,
                                         const float* __restrict__ sl,
                                         const float* __restrict__ tp,
                                         const float* __restrict__ tw,
                                         float& num, float& den) {
    float f = floorf(x);
    int   j = (int)f + 1;
    j = max(0, min(j, C_CLASSES + 1));
    float a  = ea[j];
    float s  = sl[j];
    float ip = fmaf(s, x - f, a);
    float p  = tp[t];
    float w  = tw[t];
    float d  = ip - p;
    num = fmaf(d * d, w, num);
    den += w;
}

__global__ void __launch_bounds__(256, 8)
owe_kernel(const float4* __restrict__ inp4,
           const int4*  __restrict__ tgt4,
           const float* __restrict__ weight,
           const float* __restrict__ dist,
           int n4,
           const float* __restrict__ inp_tail,
           const int*   __restrict__ tgt_tail,
           int tail_start, int n_total,
           float* __restrict__ out) {
    // 4 tables x NREP replicas x 8-word stride.
    __shared__ float s_ea[NREP * 8];   // entries 0..6 used
    __shared__ float s_sl[NREP * 8];   // entries 0..6 used
    __shared__ float s_tp[NREP * 8];   // entries 0..4 used
    __shared__ float s_tw[NREP * 8];   // entries 0..4 used

    if (threadIdx.x == 0) {
        float ds[C_CLASSES], cs[C_CLASSES];
        float ext[C_CLASSES + 3];
        float c = 0.f;
        #pragma unroll
        for (int i = 0; i < C_CLASSES; i++) { ds[i] = dist[i]; c += ds[i]; cs[i] = c; }
        float inv = 1.0f / (2.0f * cs[C_CLASSES - 1] - ds[0] - ds[C_CLASSES - 1]);
        ext[0] = -1.0f / (float)(C_CLASSES - 1);
        #pragma unroll
        for (int i = 0; i < C_CLASSES; i++)
            ext[i + 1] = (2.0f * cs[i] - ds[i] - ds[0]) * inv;
        ext[C_CLASSES + 1] = (float)C_CLASSES / (float)(C_CLASSES - 1);
        ext[C_CLASSES + 2] = ext[C_CLASSES + 1];   // pad so sl[C+1] is defined
        #pragma unroll
        for (int r = 0; r < NREP; r++) {
            #pragma unroll
            for (int jj = 0; jj <= C_CLASSES + 1; jj++) {
                s_ea[r * 8 + jj] = ext[jj];
                s_sl[r * 8 + jj] = ext[jj + 1] - ext[jj];
            }
            #pragma unroll
            for (int i = 0; i < C_CLASSES; i++) {
                s_tp[r * 8 + i] = ext[i + 1];
                s_tw[r * 8 + i] = weight[i];
            }
        }
    }
    __syncthreads();

    const int rep = (threadIdx.x & (NREP - 1)) * 8;
    const float* __restrict__ ea = s_ea + rep;
    const float* __restrict__ sl = s_sl + rep;
    const float* __restrict__ tp = s_tp + rep;
    const float* __restrict__ tw = s_tw + rep;

    // Split accumulators: halve the serial FADD chains.
    float num0 = 0.0f, num1 = 0.0f;
    float den0 = 0.0f, den1 = 0.0f;

    int tid    = blockIdx.x * blockDim.x + threadIdx.x;
    int stride = gridDim.x * blockDim.x;

    int i = tid;
    for (; i + stride < n4; i += 2 * stride) {
        float4 x0 = __ldcs(&inp4[i]);
        int4   t0 = __ldcs(&tgt4[i]);
        float4 x1 = __ldcs(&inp4[i + stride]);
        int4   t1 = __ldcs(&tgt4[i + stride]);
        owe_elem(x0.x, t0.x, ea, sl, tp, tw, num0, den0);
        owe_elem(x0.y, t0.y, ea, sl, tp, tw, num1, den1);
        owe_elem(x0.z, t0.z, ea, sl, tp, tw, num0, den0);
        owe_elem(x0.w, t0.w, ea, sl, tp, tw, num1, den1);
        owe_elem(x1.x, t1.x, ea, sl, tp, tw, num0, den0);
        owe_elem(x1.y, t1.y, ea, sl, tp, tw, num1, den1);
        owe_elem(x1.z, t1.z, ea, sl, tp, tw, num0, den0);
        owe_elem(x1.w, t1.w, ea, sl, tp, tw, num1, den1);
    }
    for (; i < n4; i += stride) {
        float4 x0 = __ldcs(&inp4[i]);
        int4   t0 = __ldcs(&tgt4[i]);
        owe_elem(x0.x, t0.x, ea, sl, tp, tw, num0, den0);
        owe_elem(x0.y, t0.y, ea, sl, tp, tw, num1, den1);
        owe_elem(x0.z, t0.z, ea, sl, tp, tw, num0, den0);
        owe_elem(x0.w, t0.w, ea, sl, tp, tw, num1, den1);
    }
    for (int jj = tail_start + tid; jj < n_total; jj += stride) {
        owe_elem(inp_tail[jj], tgt_tail[jj], ea, sl, tp, tw, num0, den0);
    }

    float num = num0 + num1;
    float den = den0 + den1;

    // Warp reduction
    #pragma unroll
    for (int off = 16; off > 0; off >>= 1) {
        num += __shfl_down_sync(0xFFFFFFFFu, num, off);
        den += __shfl_down_sync(0xFFFFFFFFu, den, off);
    }

    // Block reduction
    __shared__ float s_num[8];
    __shared__ float s_den[8];
    int lane = threadIdx.x & 31;
    int warp = threadIdx.x >> 5;
    if (lane == 0) { s_num[warp] = num; s_den[warp] = den; }
    __syncthreads();
    if (warp == 0) {
        float bn = (lane < (blockDim.x >> 5)) ? s_num[lane] : 0.0f;
        float bd = (lane < (blockDim.x >> 5)) ? s_den[lane] : 0.0f;
        #pragma unroll
        for (int off = 4; off > 0; off >>= 1) {
            bn += __shfl_down_sync(0xFFFFFFFFu, bn, off);
            bd += __shfl_down_sync(0xFFFFFFFFu, bd, off);
        }
        if (lane == 0) {
            atomicAdd(&g_acc[0], (double)bn);
            atomicAdd(&g_acc[1], (double)bd);
            __threadfence();
            unsigned done = atomicAdd(&g_count, 1u);
            if (done == gridDim.x - 1) {
                double fn = __longlong_as_double(
                    atomicExch((unsigned long long*)&g_acc[0], 0ULL));
                double fd = __longlong_as_double(
                    atomicExch((unsigned long long*)&g_acc[1], 0ULL));
                out[0] = (float)(fn / fd);
                atomicExch(&g_count, 0u);
            }
        }
    }
}

extern "C" void kernel_launch(void* const* d_in, const int* in_sizes, int n_in,
                              void* d_out, int out_size) {
    const float* inp  = (const float*)d_in[0];
    const int*   tgt  = (const int*)d_in[1];
    const float* wgt  = (const float*)d_in[2];
    const float* dist = (const float*)d_in[3];
    float* out = (float*)d_out;

    int n  = in_sizes[0];
    int n4 = n >> 2;
    int tail_start = n4 << 2;

    const int threads = 256;
    int blocks = 148 * 8;  // 1184 blocks
    int max_useful = (n4 + threads - 1) / threads;
    if (blocks > max_useful && max_useful > 0) blocks = max_useful;
    if (blocks < 1) blocks = 1;

    owe_kernel<<<blocks, threads>>>((const float4*)inp, (const int4*)tgt,
                                    wgt, dist, n4, inp, tgt, tail_start, n, out);
}